// round 17
// baseline (speedup 1.0000x reference)
#include <cuda_runtime.h>
#include <math.h>

#define FDIM  512
#define NOUT  10
#define TPB   128         // threads per block
#define RPB   128         // rows (samples) per block, one per thread
#define CHW   32          // chunk width in floats
#define NCH   (FDIM / CHW)  // 16 chunks
#define STR   36          // padded smem row stride in floats (bank-friendly)
#define PI_F  3.14159265358979323846f

__device__ __forceinline__ float dot4(float4 a, float4 b) {
    return a.x*b.x + a.y*b.y + a.z*b.z + a.w*b.w;
}
__device__ __forceinline__ float fast_tanh(float x) {
    float y;
    asm("tanh.approx.f32 %0, %1;" : "=f"(y) : "f"(x));
    return y;
}
__device__ __forceinline__ unsigned smem_u32(const void* p) {
    unsigned a;
    asm("{ .reg .u64 t; cvta.to.shared.u64 t, %1; cvt.u32.u64 %0, t; }"
        : "=r"(a) : "l"(p));
    return a;
}

// ---------------------------------------------------------------------------
// Column-chunk design: CTA owns 128 rows (1/thread). cp.async stages chunks
// of [128 rows x 32 cols]; each thread accumulates its own row's 3 dots
// (weights via broadcast LDS). No shuffles, no reduction, sim runs in-thread.
// ---------------------------------------------------------------------------
__global__ __launch_bounds__(TPB, 5)
void qnet_fused_kernel(const float* __restrict__ x,        // (B,512)
                       const float* __restrict__ pre_W,    // (3,512)
                       const float* __restrict__ pre_b,    // (3,)
                       const float* __restrict__ q_params, // (45,), rows 1..2 used
                       const float* __restrict__ post_W,   // (10,3)
                       const float* __restrict__ post_b,   // (10,)
                       float* __restrict__ out,            // (B,10)
                       int B)
{
    __shared__ float s_x[2][RPB * STR];                 // 2 x 18 KB ping-pong
    __shared__ float s_w[3 * FDIM];                     // 6 KB weights
    __shared__ float s_tc[6], s_ts[6], s_pb[3], s_pw[30], s_pbo[10];

    const int t = threadIdx.x;

    if (t < 6) {                          // parallel trig preamble (MUFU)
        float th = 0.5f * q_params[3 + t];
        s_ts[t] = __sinf(th);
        s_tc[t] = __cosf(th);
    }
    if (t < 3)  s_pb[t]  = pre_b[t];
    if (t < 30) s_pw[t]  = post_W[t];
    if (t < 10) s_pbo[t] = post_b[t];
    #pragma unroll
    for (int i = t; i < 3 * FDIM; i += TPB)
        s_w[i] = pre_W[i];

    const int base = blockIdx.x * RPB;

    // cp.async fill of one chunk: 2 threads per row, 32B (one sector) per pair
    // per k-step. thread t covers rows (t>>1) and (t>>1)+64.
    const int r0  = t >> 1;
    const int sc  = (t & 1) * 4;          // float offset of this thread's 16B
    const unsigned sb0 = smem_u32(&s_x[0][0]);
    const unsigned sb1 = smem_u32(&s_x[1][0]);

    auto fill = [&](int chunk, int bufidx) {
        unsigned db = (bufidx ? sb1 : sb0);
        #pragma unroll
        for (int h = 0; h < 2; h++) {
            int r = r0 + h * 64;
            long row = base + r;
            if (row >= B) row = B - 1;
            const float* src = x + (size_t)row * FDIM + chunk * CHW + sc;
            unsigned dst = db + (r * STR + sc) * 4;
            #pragma unroll
            for (int k = 0; k < 4; k++) {
                asm volatile("cp.async.cg.shared.global [%0], [%1], 16;"
                             :: "r"(dst + k * 32), "l"(src + k * 8) : "memory");
            }
        }
    };

    // prologue: fill both buffers
    fill(0, 0);
    asm volatile("cp.async.commit_group;" ::: "memory");
    fill(1, 1);
    asm volatile("cp.async.commit_group;" ::: "memory");

    float d0 = 0.f, d1 = 0.f, d2 = 0.f;

    #pragma unroll 1
    for (int c = 0; c < NCH; c++) {
        asm volatile("cp.async.wait_group 1;" ::: "memory");
        __syncthreads();

        const float4* xb = (const float4*)(&s_x[c & 1][t * STR]);
        const float4* w0 = (const float4*)(s_w +            c * CHW);
        const float4* w1 = (const float4*)(s_w + FDIM     + c * CHW);
        const float4* w2 = (const float4*)(s_w + 2 * FDIM + c * CHW);
        #pragma unroll
        for (int k = 0; k < CHW / 4; k++) {
            float4 xv = xb[k];
            d0 += dot4(xv, w0[k]);
            d1 += dot4(xv, w1[k]);
            d2 += dot4(xv, w2[k]);
        }
        __syncthreads();

        if (c + 2 < NCH) fill(c + 2, c & 1);
        asm volatile("cp.async.commit_group;" ::: "memory");
    }

    // -------- epilogue: this thread's row ------------------------------------
    int row = base + t;
    if (row >= B) return;

    float h0 = fast_tanh(d0 + s_pb[0]) * (PI_F * 0.25f);
    float h1 = fast_tanh(d1 + s_pb[1]) * (PI_F * 0.25f);
    float h2 = fast_tanh(d2 + s_pb[2]) * (PI_F * 0.25f);

    float st[8];
    const float inv8 = 0.3535533905932738f;    // amplitudes after H layer
    #pragma unroll
    for (int i = 0; i < 8; i++) st[i] = inv8;

    float ec, es;
    es = __sinf(h0); ec = __cosf(h0);          // encoding RY qubit 0 (stride 4)
    #pragma unroll
    for (int i = 0; i < 4; i++) {
        float a0 = st[i], a1 = st[i + 4];
        st[i]     = ec * a0 - es * a1;
        st[i + 4] = es * a0 + ec * a1;
    }
    es = __sinf(h1); ec = __cosf(h1);          // qubit 1 (stride 2)
    #pragma unroll
    for (int g = 0; g < 2; g++)
        #pragma unroll
        for (int i = 0; i < 2; i++) {
            int i0 = g * 4 + i;
            float a0 = st[i0], a1 = st[i0 + 2];
            st[i0]     = ec * a0 - es * a1;
            st[i0 + 2] = es * a0 + ec * a1;
        }
    es = __sinf(h2); ec = __cosf(h2);          // qubit 2 (stride 1)
    #pragma unroll
    for (int i0 = 0; i0 < 8; i0 += 2) {
        float a0 = st[i0], a1 = st[i0 + 1];
        st[i0]     = ec * a0 - es * a1;
        st[i0 + 1] = es * a0 + ec * a1;
    }

    #pragma unroll
    for (int k = 0; k < 2; k++) {
        float tt;
        // CNOT01: swap (4,6),(5,7); CNOT12: swap (2,3),(6,7)
        tt = st[4]; st[4] = st[6]; st[6] = tt;
        tt = st[5]; st[5] = st[7]; st[7] = tt;
        tt = st[2]; st[2] = st[3]; st[3] = tt;
        tt = st[6]; st[6] = st[7]; st[7] = tt;

        float c0 = s_tc[k * 3 + 0], sg0 = s_ts[k * 3 + 0];
        float c1 = s_tc[k * 3 + 1], sg1 = s_ts[k * 3 + 1];
        float c2 = s_tc[k * 3 + 2], sg2 = s_ts[k * 3 + 2];
        #pragma unroll
        for (int i = 0; i < 4; i++) {
            float a0 = st[i], a1 = st[i + 4];
            st[i]     = c0 * a0 - sg0 * a1;
            st[i + 4] = sg0 * a0 + c0 * a1;
        }
        #pragma unroll
        for (int g = 0; g < 2; g++)
            #pragma unroll
            for (int i = 0; i < 2; i++) {
                int i0 = g * 4 + i;
                float a0 = st[i0], a1 = st[i0 + 2];
                st[i0]     = c1 * a0 - sg1 * a1;
                st[i0 + 2] = sg1 * a0 + c1 * a1;
            }
        #pragma unroll
        for (int i0 = 0; i0 < 8; i0 += 2) {
            float a0 = st[i0], a1 = st[i0 + 1];
            st[i0]     = c2 * a0 - sg2 * a1;
            st[i0 + 1] = sg2 * a0 + c2 * a1;
        }
    }

    float p[8];
    #pragma unroll
    for (int i = 0; i < 8; i++) p[i] = st[i] * st[i];
    float z0 = (p[0] + p[1] + p[2] + p[3]) - (p[4] + p[5] + p[6] + p[7]);
    float z1 = (p[0] + p[1] + p[4] + p[5]) - (p[2] + p[3] + p[6] + p[7]);
    float z2 = (p[0] + p[2] + p[4] + p[6]) - (p[1] + p[3] + p[5] + p[7]);

    float2* op = (float2*)(out + (size_t)row * NOUT);
    #pragma unroll
    for (int k = 0; k < 5; k++) {
        float2 w;
        w.x = z0 * s_pw[(2*k)   * 3 + 0] + z1 * s_pw[(2*k)   * 3 + 1]
            + z2 * s_pw[(2*k)   * 3 + 2] + s_pbo[2*k];
        w.y = z0 * s_pw[(2*k+1) * 3 + 0] + z1 * s_pw[(2*k+1) * 3 + 1]
            + z2 * s_pw[(2*k+1) * 3 + 2] + s_pbo[2*k+1];
        op[k] = w;
    }
}

extern "C" void kernel_launch(void* const* d_in, const int* in_sizes, int n_in,
                              void* d_out, int out_size) {
    const float* x      = (const float*)d_in[0];
    const float* pre_W  = (const float*)d_in[1];
    const float* pre_b  = (const float*)d_in[2];
    const float* q_par  = (const float*)d_in[3];
    const float* post_W = (const float*)d_in[4];
    const float* post_b = (const float*)d_in[5];
    float* out = (float*)d_out;

    int B = in_sizes[0] / FDIM;

    int blocks = (B + RPB - 1) / RPB;                    // 512 for B=65536
    qnet_fused_kernel<<<blocks, TPB>>>(x, pre_W, pre_b, q_par,
                                       post_W, post_b, out, B);
}